// round 11
// baseline (speedup 1.0000x reference)
#include <cuda_runtime.h>
#include <cstdint>
#include <cstddef>

#define BB 64
#define VV 2048
#define HH 128
#define NNODE (BB*VV)      /* 131072 */
#define EE 1048576
#define CFD 47
#define EPSB 1e-5f

// ---------------- device scratch (allocation-free rule) ----------------
__device__ __align__(16) float g_Y1e[(size_t)EE*HH];      // 512MB  X@w1+b1 (pre-BN)
__device__ __align__(16) float g_H2[(size_t)EE*2*HH];     // 1GB    silu(BN1)@w2+b2 (pre-BN)
__device__ __align__(16) float g_h[(size_t)NNODE*HH];     // 64MB
__device__ __align__(16) float g_hprop[(size_t)NNODE*HH];
__device__ __align__(16) float g_y1[(size_t)NNODE*HH];
__device__ __align__(16) float g_y2[(size_t)NNODE*HH];
__device__ __align__(16) float g_hspec[(size_t)BB*HH*HH]; // 4MB
__device__ float g_stsum[2*HH];
__device__ float g_stsq[2*HH];
__device__ float g_affA[2*HH];
__device__ float g_affC[2*HH];
__device__ float g_outacc[BB];

__device__ __forceinline__ float siluf(float x){ return x/(1.f+__expf(-x)); }

// ---- packed fp32x2 FMA (Blackwell FFMA2) ----
__device__ __forceinline__ void ffma2(uint64_t& c, uint64_t a, uint64_t b){
    asm("fma.rn.f32x2 %0, %1, %2, %0;" : "+l"(c) : "l"(a), "l"(b));
}
__device__ __forceinline__ uint64_t dup2(float x){
    uint64_t r; asm("mov.b64 %0, {%1, %1};" : "=l"(r) : "f"(x)); return r;
}
__device__ __forceinline__ float2 unp2(uint64_t v){
    float2 f; asm("mov.b64 {%0, %1}, %2;" : "=f"(f.x), "=f"(f.y) : "l"(v)); return f;
}
__device__ __forceinline__ void red4(float* dst, float a, float b, float c, float d){
    asm volatile("red.global.add.v4.f32 [%0], {%1,%2,%3,%4};"
                 :: "l"(dst), "f"(a), "f"(b), "f"(c), "f"(d) : "memory");
}

// ---------------- zero kernels ----------------
__global__ void k_zero_h(){
    size_t i=(size_t)blockIdx.x*blockDim.x+threadIdx.x;
    ((float4*)g_h)[i]=make_float4(0.f,0.f,0.f,0.f);
    if(blockIdx.x==0&&threadIdx.x<BB) g_outacc[threadIdx.x]=0.f;
}
__global__ void k_zero_spec(){
    size_t i=(size_t)blockIdx.x*blockDim.x+threadIdx.x;
    ((float4*)g_hspec)[i]=make_float4(0.f,0.f,0.f,0.f);
}
__global__ void k_zero_st(){
    int t=threadIdx.x;
    if(t<2*HH){ g_stsum[t]=0.f; g_stsq[t]=0.f; }
}

// ---------------- GEMM1: Y1 = X@w1 + b1 (K=47), with column stats ----------------
__global__ __launch_bounds__(256) void k_gemm1(const float* __restrict__ X,
                                               const float* __restrict__ w1,
                                               const float* __restrict__ b1){
    __shared__ float ws[CFD*HH];
    __shared__ float xs[128*48];
    int t=threadIdx.x, ty=t>>4, tx=t&15;
    size_t m0=(size_t)blockIdx.x*128;
    for(int i=t;i<CFD*HH;i+=256) ws[i]=w1[i];
    const float* src=X+m0*CFD;
    for(int i=t;i<128*CFD;i+=256) xs[(i/CFD)*48+(i%CFD)]=src[i];
    __syncthreads();
    uint64_t acc[8][4]={};
    for(int k=0;k<CFD;k++){
        ulonglong2 q0=*(const ulonglong2*)&ws[k*HH+tx*8];
        ulonglong2 q1=*(const ulonglong2*)&ws[k*HH+tx*8+4];
        uint64_t bp[4]={q0.x,q0.y,q1.x,q1.y};
        #pragma unroll
        for(int ri=0;ri<8;ri++){
            uint64_t ad=dup2(xs[(ty*8+ri)*48+k]);
            #pragma unroll
            for(int cp=0;cp<4;cp++) ffma2(acc[ri][cp],ad,bp[cp]);
        }
    }
    float bb[8];
    #pragma unroll
    for(int ci=0;ci<8;ci++) bb[ci]=b1[tx*8+ci];
    float ls[8]={}, lq[8]={};
    #pragma unroll
    for(int ri=0;ri<8;ri++){
        float v[8];
        #pragma unroll
        for(int cp=0;cp<4;cp++){ float2 p=unp2(acc[ri][cp]); v[2*cp]=p.x; v[2*cp+1]=p.y; }
        #pragma unroll
        for(int ci=0;ci<8;ci++){ v[ci]+=bb[ci]; ls[ci]+=v[ci]; lq[ci]+=v[ci]*v[ci]; }
        size_t row=m0+ty*8+ri;
        *(float4*)&g_Y1e[row*HH+tx*8]  =make_float4(v[0],v[1],v[2],v[3]);
        *(float4*)&g_Y1e[row*HH+tx*8+4]=make_float4(v[4],v[5],v[6],v[7]);
    }
    __syncthreads();
    #pragma unroll
    for(int ci=0;ci<8;ci++) ws[ty*128+tx*8+ci]=ls[ci];
    __syncthreads();
    if(t<128){ float s=0.f; for(int q=0;q<16;q++) s+=ws[q*128+t]; atomicAdd(&g_stsum[t],s); }
    __syncthreads();
    #pragma unroll
    for(int ci=0;ci<8;ci++) ws[ty*128+tx*8+ci]=lq[ci];
    __syncthreads();
    if(t<128){ float s=0.f; for(int q=0;q<16;q++) s+=ws[q*128+t]; atomicAdd(&g_stsq[t],s); }
}

// ---------------- fold stats -> affine ----------------
__global__ void k_fold(int ncols, float invn,
                       const float* __restrict__ g, const float* __restrict__ be){
    int j=threadIdx.x;
    if(j<ncols){
        float m=g_stsum[j]*invn;
        float var=g_stsq[j]*invn-m*m;
        float A=g[j]*rsqrtf(var+EPSB);
        g_affA[j]=A;
        g_affC[j]=be[j]-A*m;
    }
}

// ---------------- generic 128x128 tiled GEMM (FFMA2 + reg double-buffer) ----------------
__global__ __launch_bounds__(256,2) void k_mm(int mode, int asel, int csel,
        const float* __restrict__ eigs,
        const float* __restrict__ Bw, int ldb,
        const float* __restrict__ bias,
        int ldc, int Kdim, int do_stats)
{
    __shared__ float As[2][16*128];
    __shared__ float Bs[2][16*128];
    const float* A=(asel==0)?g_Y1e:(asel==1)?g_h:g_y1;
    float* Cout=(csel==0)?g_H2:(csel==1)?g_hprop:(csel==2)?g_y1:g_y2;
    int t=threadIdx.x, ty=t>>4, tx=t&15;
    size_t m0=(size_t)blockIdx.x*128;
    int bcol=blockIdx.y*128;
    const float* Abase=A;
    const float* Bbase=Bw;
    if(mode==3){
        size_t b=m0>>11;
        Abase=eigs+(b*4097+1)*128+(m0&2047)*128;
        Bbase=g_hspec+b*16384;
    }
    int am=t>>1, akq=(t&1)*8;
    int bk=t>>4, bn=(t&15)*8;

    float av[8], bv[8];
    #define LDCHUNK(k0v, avr, bvr) do{ \
        int _k0=(k0v); \
        const float* _ap; \
        if(mode==1)      _ap=(_k0+akq<128)?(g_h+(m0+am)*128+_k0+akq):(g_hprop+(m0+am)*128+(_k0+akq-128)); \
        else if(mode==3) _ap=Abase+(size_t)am*128+_k0+akq; \
        else             _ap=Abase+(m0+am)*128+_k0+akq; \
        float4 _v0=*(const float4*)_ap, _v1=*(const float4*)(_ap+4); \
        avr[0]=_v0.x; avr[1]=_v0.y; avr[2]=_v0.z; avr[3]=_v0.w; \
        avr[4]=_v1.x; avr[5]=_v1.y; avr[6]=_v1.z; avr[7]=_v1.w; \
        const float* _bp=Bbase+(size_t)(_k0+bk)*ldb+bcol+bn; \
        float4 _b0=*(const float4*)_bp, _b1=*(const float4*)(_bp+4); \
        bvr[0]=_b0.x; bvr[1]=_b0.y; bvr[2]=_b0.z; bvr[3]=_b0.w; \
        bvr[4]=_b1.x; bvr[5]=_b1.y; bvr[6]=_b1.z; bvr[7]=_b1.w; \
    }while(0)

    uint64_t acc[8][4]={};
    LDCHUNK(0, av, bv);
    for(int k0=0;k0<Kdim;k0+=16){
        int st=(k0>>4)&1;
        #pragma unroll
        for(int i=0;i<8;i++){
            float x=av[i];
            if(mode==2){ int kg=k0+akq+i; x=siluf(g_affA[kg]*x+g_affC[kg]); }
            As[st][(akq+i)*128+am]=x;
        }
        *(float4*)&Bs[st][bk*128+bn]  =make_float4(bv[0],bv[1],bv[2],bv[3]);
        *(float4*)&Bs[st][bk*128+bn+4]=make_float4(bv[4],bv[5],bv[6],bv[7]);
        __syncthreads();
        float an[8], bn2[8];
        if(k0+16<Kdim) LDCHUNK(k0+16, an, bn2);
        #pragma unroll
        for(int kk=0;kk<16;kk++){
            float4 a0=*(const float4*)&As[st][kk*128+ty*8];
            float4 a1=*(const float4*)&As[st][kk*128+ty*8+4];
            ulonglong2 q0=*(const ulonglong2*)&Bs[st][kk*128+tx*8];
            ulonglong2 q1=*(const ulonglong2*)&Bs[st][kk*128+tx*8+4];
            uint64_t bp2[4]={q0.x,q0.y,q1.x,q1.y};
            float aa[8]={a0.x,a0.y,a0.z,a0.w,a1.x,a1.y,a1.z,a1.w};
            #pragma unroll
            for(int ri=0;ri<8;ri++){
                uint64_t ad=dup2(aa[ri]);
                #pragma unroll
                for(int cp=0;cp<4;cp++) ffma2(acc[ri][cp],ad,bp2[cp]);
            }
        }
        __syncthreads();
        #pragma unroll
        for(int i=0;i<8;i++){ av[i]=an[i]; bv[i]=bn2[i]; }
    }
    #undef LDCHUNK

    float bb[8];
    #pragma unroll
    for(int ci=0;ci<8;ci++) bb[ci]=bias?bias[bcol+tx*8+ci]:0.f;
    float ls[8]={}, lq[8]={};
    #pragma unroll
    for(int ri=0;ri<8;ri++){
        float v[8];
        #pragma unroll
        for(int cp=0;cp<4;cp++){ float2 p=unp2(acc[ri][cp]); v[2*cp]=p.x; v[2*cp+1]=p.y; }
        #pragma unroll
        for(int ci=0;ci<8;ci++){ v[ci]+=bb[ci]; ls[ci]+=v[ci]; lq[ci]+=v[ci]*v[ci]; }
        size_t row=m0+ty*8+ri;
        *(float4*)&Cout[row*(size_t)ldc+bcol+tx*8]  =make_float4(v[0],v[1],v[2],v[3]);
        *(float4*)&Cout[row*(size_t)ldc+bcol+tx*8+4]=make_float4(v[4],v[5],v[6],v[7]);
    }
    if(do_stats){
        __syncthreads();
        #pragma unroll
        for(int ci=0;ci<8;ci++) As[0][ty*128+tx*8+ci]=ls[ci];
        __syncthreads();
        if(t<128){ float s=0.f; for(int q=0;q<16;q++) s+=As[0][q*128+t]; atomicAdd(&g_stsum[bcol+t],s); }
        __syncthreads();
        #pragma unroll
        for(int ci=0;ci<8;ci++) As[0][ty*128+tx*8+ci]=lq[ci];
        __syncthreads();
        if(t<128){ float s=0.f; for(int q=0;q<16;q++) s+=As[0][q*128+t]; atomicAdd(&g_stsq[bcol+t],s); }
    }
}

// ---------------- msg activation + segment-sum scatter (vector red) ----------------
__global__ __launch_bounds__(256) void k_msg(const int* __restrict__ nbr){
    int warp=threadIdx.x>>5, lane=threadIdx.x&31;
    size_t e=(size_t)blockIdx.x*8+warp;
    const float* h2=g_H2+e*256;
    int j=lane*4;
    float4 f=*(const float4*)(h2+j);
    float4 c=*(const float4*)(h2+128+j);
    float fr[4]={f.x,f.y,f.z,f.w}, cr[4]={c.x,c.y,c.z,c.w}, o[4];
    #pragma unroll
    for(int s=0;s<4;s++){
        int jj=j+s;
        float fv=g_affA[jj]*fr[s]+g_affC[jj];
        float cv=g_affA[128+jj]*cr[s]+g_affC[128+jj];
        float sg=1.f/(1.f+__expf(-fv));
        float sp=fmaxf(cv,0.f)+log1pf(__expf(-fabsf(cv)));
        o[s]=sg*sp;
    }
    float* dst=g_h+(size_t)nbr[e]*128+j;
    red4(dst,o[0],o[1],o[2],o[3]);
}

// ---------------- h_spec (FFMA2 + reg double-buffer) ----------------
__global__ __launch_bounds__(256,2) void k_spec(const float* __restrict__ eigs){
    __shared__ float As[2][16*128];
    __shared__ float Bs[2][16*128];
    int t=threadIdx.x, ty=t>>4, tx=t&15;
    int b=blockIdx.x>>2, c=blockIdx.x&3;
    int v0=c*512;
    const float* Abase=eigs+((size_t)b*4097+1+2048)*128;
    const float* Hbase=g_h+((size_t)b*2048)*128;
    int vr=t>>4, cq=(t&15)*8;
    uint64_t acc[8][4]={};
    float av[8], bv[8];
    #define LDV(vtv, avr, bvr) do{ \
        const float* _ap=Abase+(size_t)(v0+(vtv)+vr)*128+cq; \
        float4 _a0=*(const float4*)_ap, _a1=*(const float4*)(_ap+4); \
        avr[0]=_a0.x; avr[1]=_a0.y; avr[2]=_a0.z; avr[3]=_a0.w; \
        avr[4]=_a1.x; avr[5]=_a1.y; avr[6]=_a1.z; avr[7]=_a1.w; \
        const float* _bp=Hbase+(size_t)(v0+(vtv)+vr)*128+cq; \
        float4 _b0=*(const float4*)_bp, _b1=*(const float4*)(_bp+4); \
        bvr[0]=_b0.x; bvr[1]=_b0.y; bvr[2]=_b0.z; bvr[3]=_b0.w; \
        bvr[4]=_b1.x; bvr[5]=_b1.y; bvr[6]=_b1.z; bvr[7]=_b1.w; \
    }while(0)
    LDV(0, av, bv);
    for(int vt=0;vt<512;vt+=16){
        int st=(vt>>4)&1;
        *(float4*)&As[st][vr*128+cq]  =make_float4(av[0],av[1],av[2],av[3]);
        *(float4*)&As[st][vr*128+cq+4]=make_float4(av[4],av[5],av[6],av[7]);
        *(float4*)&Bs[st][vr*128+cq]  =make_float4(bv[0],bv[1],bv[2],bv[3]);
        *(float4*)&Bs[st][vr*128+cq+4]=make_float4(bv[4],bv[5],bv[6],bv[7]);
        __syncthreads();
        float an[8], bn2[8];
        if(vt+16<512) LDV(vt+16, an, bn2);
        #pragma unroll
        for(int vv=0;vv<16;vv++){
            float4 a0=*(const float4*)&As[st][vv*128+ty*8];
            float4 a1=*(const float4*)&As[st][vv*128+ty*8+4];
            ulonglong2 q0=*(const ulonglong2*)&Bs[st][vv*128+tx*8];
            ulonglong2 q1=*(const ulonglong2*)&Bs[st][vv*128+tx*8+4];
            uint64_t bp2[4]={q0.x,q0.y,q1.x,q1.y};
            float aa[8]={a0.x,a0.y,a0.z,a0.w,a1.x,a1.y,a1.z,a1.w};
            #pragma unroll
            for(int ri=0;ri<8;ri++){
                uint64_t ad=dup2(aa[ri]);
                #pragma unroll
                for(int cp=0;cp<4;cp++) ffma2(acc[ri][cp],ad,bp2[cp]);
            }
        }
        __syncthreads();
        #pragma unroll
        for(int i=0;i<8;i++){ av[i]=an[i]; bv[i]=bn2[i]; }
    }
    #undef LDV
    float* dst=g_hspec+(size_t)b*16384;
    #pragma unroll
    for(int ri=0;ri<8;ri++){
        #pragma unroll
        for(int cp=0;cp<4;cp++){
            float2 p=unp2(acc[ri][cp]);
            atomicAdd(&dst[(ty*8+ri)*128+tx*8+2*cp],  p.x);
            atomicAdd(&dst[(ty*8+ri)*128+tx*8+2*cp+1],p.y);
        }
    }
}

// ---------------- h_spec *= exp(-lam*t) ----------------
__global__ void k_coeff(const float* __restrict__ eigs, const float* __restrict__ pt){
    int i=blockIdx.x*blockDim.x+threadIdx.x;
    int b=i>>14, k=(i>>7)&127, hcol=i&127;
    float lam=eigs[(size_t)b*4097*128+k];
    float tt=fmaxf(pt[hcol],1e-6f);
    g_hspec[i]*=__expf(-lam*tt);
}

// ---------------- h += affA*y2 + affC ----------------
__global__ void k_update(){
    size_t i=(size_t)blockIdx.x*blockDim.x+threadIdx.x;
    int j=(int)((i*4)&127);
    float4 y=((const float4*)g_y2)[i];
    float4 h=((float4*)g_h)[i];
    h.x+=g_affA[j+0]*y.x+g_affC[j+0];
    h.y+=g_affA[j+1]*y.y+g_affC[j+1];
    h.z+=g_affA[j+2]*y.z+g_affC[j+2];
    h.w+=g_affA[j+3]*y.w+g_affC[j+3];
    ((float4*)g_h)[i]=h;
}

// ---------------- final projection + mean over V ----------------
__global__ __launch_bounds__(256) void k_out(const float* __restrict__ wo2){
    __shared__ float part[8];
    int warp=threadIdx.x>>5, lane=threadIdx.x&31;
    size_t row=(size_t)blockIdx.x*8+warp;
    int j=lane*4;
    float4 y=*(const float4*)&g_y1[row*128+j];
    float4 w=*(const float4*)&wo2[j];
    float v=0.f;
    v+=siluf(g_affA[j+0]*y.x+g_affC[j+0])*w.x;
    v+=siluf(g_affA[j+1]*y.y+g_affC[j+1])*w.y;
    v+=siluf(g_affA[j+2]*y.z+g_affC[j+2])*w.z;
    v+=siluf(g_affA[j+3]*y.w+g_affC[j+3])*w.w;
    #pragma unroll
    for(int s=16;s>0;s>>=1) v+=__shfl_xor_sync(0xffffffffu,v,s);
    if(lane==0) part[warp]=v;
    __syncthreads();
    if(threadIdx.x==0){
        float s=0.f;
        #pragma unroll
        for(int q=0;q<8;q++) s+=part[q];
        atomicAdd(&g_outacc[blockIdx.x>>8],s);
    }
}

__global__ void k_final(float* out, const float* __restrict__ bo2){
    int b=threadIdx.x;
    if(b<BB) out[b]=g_outacc[b]*(1.f/(float)VV)+bo2[0];
}

// ---------------- launch ----------------
extern "C" void kernel_launch(void* const* d_in, const int* in_sizes, int n_in,
                              void* d_out, int out_size){
    const float* chem =(const float*)d_in[0];
    const int*   nbr  =(const int*)  d_in[1];
    const float* eigs =(const float*)d_in[2];
    const float* w1   =(const float*)d_in[3];
    const float* b1   =(const float*)d_in[4];
    const float* g1   =(const float*)d_in[5];
    const float* be1  =(const float*)d_in[6];
    const float* w2   =(const float*)d_in[7];
    const float* b2   =(const float*)d_in[8];
    const float* g2   =(const float*)d_in[9];
    const float* be2  =(const float*)d_in[10];
    const float* prop =(const float*)d_in[11];
    const float* pw1  =(const float*)d_in[12];
    const float* pb1  =(const float*)d_in[13];
    const float* pg1  =(const float*)d_in[14];
    const float* pbe1 =(const float*)d_in[15];
    const float* pw2  =(const float*)d_in[16];
    const float* pb2  =(const float*)d_in[17];
    const float* pg2  =(const float*)d_in[18];
    const float* pbe2 =(const float*)d_in[19];
    const float* wo1  =(const float*)d_in[20];
    const float* bo1  =(const float*)d_in[21];
    const float* go1  =(const float*)d_in[22];
    const float* beo1 =(const float*)d_in[23];
    const float* wo2  =(const float*)d_in[24];
    const float* bo2  =(const float*)d_in[25];
    (void)in_sizes; (void)n_in; (void)out_size;

    k_zero_h<<<4096,1024>>>();
    k_zero_st<<<1,256>>>();
    k_gemm1<<<EE/128,256>>>(chem,w1,b1);
    k_fold<<<1,256>>>(128,1.f/(float)EE,g1,be1);
    k_zero_st<<<1,256>>>();
    k_mm<<<dim3(EE/128,2),256>>>(2,0,0,nullptr,w2,256,b2,256,128,1);
    k_fold<<<1,256>>>(256,1.f/(float)EE,g2,be2);
    k_msg<<<EE/8,256>>>(nbr);

    for(int l=0;l<3;l++){
        k_zero_spec<<<256,1024>>>();
        k_spec<<<256,256>>>(eigs);
        k_coeff<<<4096,256>>>(eigs,prop+l*128);
        k_mm<<<dim3(NNODE/128,1),256>>>(3,1,1,eigs,nullptr,128,nullptr,128,128,0);
        k_zero_st<<<1,256>>>();
        k_mm<<<dim3(NNODE/128,1),256>>>(1,1,2,nullptr,pw1+(size_t)l*256*128,128,pb1+l*128,128,256,1);
        k_fold<<<1,256>>>(128,1.f/(float)NNODE,pg1+l*128,pbe1+l*128);
        k_zero_st<<<1,256>>>();
        k_mm<<<dim3(NNODE/128,1),256>>>(2,2,3,nullptr,pw2+(size_t)l*128*128,128,pb2+l*128,128,128,1);
        k_fold<<<1,256>>>(128,1.f/(float)NNODE,pg2+l*128,pbe2+l*128);
        k_update<<<16384,256>>>();
    }

    k_zero_st<<<1,256>>>();
    k_mm<<<dim3(NNODE/128,1),256>>>(0,1,2,nullptr,wo1,128,bo1,128,128,1);
    k_fold<<<1,256>>>(128,1.f/(float)NNODE,go1,beo1);
    k_out<<<NNODE/8,256>>>(wo2);
    k_final<<<1,64>>>((float*)d_out,bo2);
}

// round 13
// speedup vs baseline: 1.5189x; 1.5189x over previous
#include <cuda_runtime.h>
#include <cstdint>
#include <cstddef>

#define BB 64
#define VV 2048
#define HH 128
#define NNODE (BB*VV)      /* 131072 */
#define EE 1048576
#define CFD 47
#define EPSB 1e-5f

// ---------------- device scratch (allocation-free rule) ----------------
__device__ __align__(16) float g_Y1e[(size_t)EE*HH];      // 512MB  X@w1+b1 (pre-BN)
__device__ __align__(16) float g_H2[(size_t)EE*2*HH];     // 1GB    silu(BN1)@w2+b2 (pre-BN)
__device__ __align__(16) float g_h[(size_t)NNODE*HH];     // 64MB
__device__ __align__(16) float g_hprop[(size_t)NNODE*HH];
__device__ __align__(16) float g_y1[(size_t)NNODE*HH];
__device__ __align__(16) float g_y2[(size_t)NNODE*HH];
__device__ __align__(16) float g_hspec[(size_t)BB*HH*HH]; // 4MB
__device__ float g_stsum[2*HH];
__device__ float g_stsq[2*HH];
__device__ float g_affA[2*HH];
__device__ float g_affC[2*HH];
__device__ float g_outacc[BB];

__device__ __forceinline__ float siluf(float x){ return x/(1.f+__expf(-x)); }

// ---- packed fp32x2 FMA (Blackwell FFMA2) ----
__device__ __forceinline__ void ffma2(uint64_t& c, uint64_t a, uint64_t b){
    asm("fma.rn.f32x2 %0, %1, %2, %0;" : "+l"(c) : "l"(a), "l"(b));
}
__device__ __forceinline__ uint64_t dup2(float x){
    uint64_t r; asm("mov.b64 %0, {%1, %1};" : "=l"(r) : "f"(x)); return r;
}
__device__ __forceinline__ float2 unp2(uint64_t v){
    float2 f; asm("mov.b64 {%0, %1}, %2;" : "=f"(f.x), "=f"(f.y) : "l"(v)); return f;
}
__device__ __forceinline__ void red4(float* dst, float a, float b, float c, float d){
    asm volatile("red.global.add.v4.f32 [%0], {%1,%2,%3,%4};"
                 :: "l"(dst), "f"(a), "f"(b), "f"(c), "f"(d) : "memory");
}

// ---------------- zero kernels ----------------
__global__ void k_zero_h(){
    size_t i=(size_t)blockIdx.x*blockDim.x+threadIdx.x;
    ((float4*)g_h)[i]=make_float4(0.f,0.f,0.f,0.f);
    if(blockIdx.x==0&&threadIdx.x<BB) g_outacc[threadIdx.x]=0.f;
}
__global__ void k_zero_spec(){
    size_t i=(size_t)blockIdx.x*blockDim.x+threadIdx.x;
    ((float4*)g_hspec)[i]=make_float4(0.f,0.f,0.f,0.f);
}
__global__ void k_zero_st(){
    int t=threadIdx.x;
    if(t<2*HH){ g_stsum[t]=0.f; g_stsq[t]=0.f; }
}

// ---------------- GEMM1: Y1 = X@w1 + b1 (K=47), with column stats ----------------
__global__ __launch_bounds__(256) void k_gemm1(const float* __restrict__ X,
                                               const float* __restrict__ w1,
                                               const float* __restrict__ b1){
    __shared__ float ws[CFD*HH];
    __shared__ float xs[128*48];
    int t=threadIdx.x, ty=t>>4, tx=t&15;
    size_t m0=(size_t)blockIdx.x*128;
    for(int i=t;i<CFD*HH;i+=256) ws[i]=w1[i];
    const float* src=X+m0*CFD;
    for(int i=t;i<128*CFD;i+=256) xs[(i/CFD)*48+(i%CFD)]=src[i];
    __syncthreads();
    uint64_t acc[8][4]={};
    for(int k=0;k<CFD;k++){
        ulonglong2 q0=*(const ulonglong2*)&ws[k*HH+tx*8];
        ulonglong2 q1=*(const ulonglong2*)&ws[k*HH+tx*8+4];
        uint64_t bp[4]={q0.x,q0.y,q1.x,q1.y};
        #pragma unroll
        for(int ri=0;ri<8;ri++){
            uint64_t ad=dup2(xs[(ty*8+ri)*48+k]);
            #pragma unroll
            for(int cp=0;cp<4;cp++) ffma2(acc[ri][cp],ad,bp[cp]);
        }
    }
    float bb[8];
    #pragma unroll
    for(int ci=0;ci<8;ci++) bb[ci]=b1[tx*8+ci];
    float ls[8]={}, lq[8]={};
    #pragma unroll
    for(int ri=0;ri<8;ri++){
        float v[8];
        #pragma unroll
        for(int cp=0;cp<4;cp++){ float2 p=unp2(acc[ri][cp]); v[2*cp]=p.x; v[2*cp+1]=p.y; }
        #pragma unroll
        for(int ci=0;ci<8;ci++){ v[ci]+=bb[ci]; ls[ci]+=v[ci]; lq[ci]+=v[ci]*v[ci]; }
        size_t row=m0+ty*8+ri;
        *(float4*)&g_Y1e[row*HH+tx*8]  =make_float4(v[0],v[1],v[2],v[3]);
        *(float4*)&g_Y1e[row*HH+tx*8+4]=make_float4(v[4],v[5],v[6],v[7]);
    }
    __syncthreads();
    #pragma unroll
    for(int ci=0;ci<8;ci++) ws[ty*128+tx*8+ci]=ls[ci];
    __syncthreads();
    if(t<128){ float s=0.f; for(int q=0;q<16;q++) s+=ws[q*128+t]; atomicAdd(&g_stsum[t],s); }
    __syncthreads();
    #pragma unroll
    for(int ci=0;ci<8;ci++) ws[ty*128+tx*8+ci]=lq[ci];
    __syncthreads();
    if(t<128){ float s=0.f; for(int q=0;q<16;q++) s+=ws[q*128+t]; atomicAdd(&g_stsq[t],s); }
}

// ---------------- fold stats -> affine ----------------
__global__ void k_fold(int ncols, float invn,
                       const float* __restrict__ g, const float* __restrict__ be){
    int j=threadIdx.x;
    if(j<ncols){
        float m=g_stsum[j]*invn;
        float var=g_stsq[j]*invn-m*m;
        float A=g[j]*rsqrtf(var+EPSB);
        g_affA[j]=A;
        g_affC[j]=be[j]-A*m;
    }
}

// ---------------- generic 128x128 tiled GEMM (FFMA2, K-chunk 32) ----------------
// mode 0: plain A           mode 1: A = concat(g_h, g_hprop), Kdim=256
// mode 2: A elem -> silu(affA*a+affC)
// mode 3: A = evecs from eigs (per-batch), B = g_hspec per-batch
// asel: 0=g_Y1e 1=g_h 2=g_y1 ; csel: 0=g_H2 1=g_hprop 2=g_y1 3=g_y2
__global__ __launch_bounds__(256) void k_mm(int mode, int asel, int csel,
        const float* __restrict__ eigs,
        const float* __restrict__ Bw, int ldb,
        const float* __restrict__ bias,
        int ldc, int Kdim, int do_stats)
{
    __shared__ float As[32*128];
    __shared__ float Bs[32*128];
    const float* A=(asel==0)?g_Y1e:(asel==1)?g_h:g_y1;
    float* Cout=(csel==0)?g_H2:(csel==1)?g_hprop:(csel==2)?g_y1:g_y2;
    int t=threadIdx.x, ty=t>>4, tx=t&15;
    size_t m0=(size_t)blockIdx.x*128;
    int bcol=blockIdx.y*128;
    const float* Abase=A;
    const float* Bbase=Bw;
    if(mode==3){
        size_t b=m0>>11;
        Abase=eigs+(b*4097+1)*128+(m0&2047)*128;
        Bbase=g_hspec+b*16384;
    }
    uint64_t acc[8][4]={};
    int am=t>>1, akq=(t&1)*8;
    int bk=t>>4, bn=(t&15)*8;
    for(int k0=0;k0<Kdim;k0+=32){
        #pragma unroll
        for(int hq=0;hq<2;hq++){
            int kq=hq*16+akq;
            int kgb=k0+kq;
            const float* ap;
            if(mode==1)      ap=(kgb<128)?(g_h+(m0+am)*128+kgb):(g_hprop+(m0+am)*128+(kgb-128));
            else if(mode==3) ap=Abase+(size_t)am*128+kgb;
            else             ap=Abase+(m0+am)*128+kgb;
            float4 v0=*(const float4*)ap, v1=*(const float4*)(ap+4);
            float av[8]={v0.x,v0.y,v0.z,v0.w,v1.x,v1.y,v1.z,v1.w};
            if(mode==2){
                #pragma unroll
                for(int i=0;i<8;i++){ int kg=kgb+i; av[i]=siluf(g_affA[kg]*av[i]+g_affC[kg]); }
            }
            #pragma unroll
            for(int i=0;i<8;i++) As[(kq+i)*128+am]=av[i];
        }
        #pragma unroll
        for(int hq=0;hq<2;hq++){
            int kb=bk+hq*16;
            const float* bp=Bbase+(size_t)(k0+kb)*ldb+bcol+bn;
            *(float4*)&Bs[kb*128+bn]  =*(const float4*)bp;
            *(float4*)&Bs[kb*128+bn+4]=*(const float4*)(bp+4);
        }
        __syncthreads();
        #pragma unroll
        for(int kk=0;kk<32;kk++){
            float4 a0=*(const float4*)&As[kk*128+ty*8];
            float4 a1=*(const float4*)&As[kk*128+ty*8+4];
            ulonglong2 q0=*(const ulonglong2*)&Bs[kk*128+tx*8];
            ulonglong2 q1=*(const ulonglong2*)&Bs[kk*128+tx*8+4];
            uint64_t bp2[4]={q0.x,q0.y,q1.x,q1.y};
            float aa[8]={a0.x,a0.y,a0.z,a0.w,a1.x,a1.y,a1.z,a1.w};
            #pragma unroll
            for(int ri=0;ri<8;ri++){
                uint64_t ad=dup2(aa[ri]);
                #pragma unroll
                for(int cp=0;cp<4;cp++) ffma2(acc[ri][cp],ad,bp2[cp]);
            }
        }
        __syncthreads();
    }
    float bb[8];
    #pragma unroll
    for(int ci=0;ci<8;ci++) bb[ci]=bias?bias[bcol+tx*8+ci]:0.f;
    float ls[8]={}, lq[8]={};
    #pragma unroll
    for(int ri=0;ri<8;ri++){
        float v[8];
        #pragma unroll
        for(int cp=0;cp<4;cp++){ float2 p=unp2(acc[ri][cp]); v[2*cp]=p.x; v[2*cp+1]=p.y; }
        #pragma unroll
        for(int ci=0;ci<8;ci++){ v[ci]+=bb[ci]; ls[ci]+=v[ci]; lq[ci]+=v[ci]*v[ci]; }
        size_t row=m0+ty*8+ri;
        *(float4*)&Cout[row*(size_t)ldc+bcol+tx*8]  =make_float4(v[0],v[1],v[2],v[3]);
        *(float4*)&Cout[row*(size_t)ldc+bcol+tx*8+4]=make_float4(v[4],v[5],v[6],v[7]);
    }
    if(do_stats){
        __syncthreads();
        #pragma unroll
        for(int ci=0;ci<8;ci++) As[ty*128+tx*8+ci]=ls[ci];
        __syncthreads();
        if(t<128){ float s=0.f; for(int q=0;q<16;q++) s+=As[q*128+t]; atomicAdd(&g_stsum[bcol+t],s); }
        __syncthreads();
        #pragma unroll
        for(int ci=0;ci<8;ci++) As[ty*128+tx*8+ci]=lq[ci];
        __syncthreads();
        if(t<128){ float s=0.f; for(int q=0;q<16;q++) s+=As[q*128+t]; atomicAdd(&g_stsq[bcol+t],s); }
    }
}

// ---------------- msg activation + segment-sum scatter (vector red) ----------------
__global__ __launch_bounds__(256) void k_msg(const int* __restrict__ nbr){
    int warp=threadIdx.x>>5, lane=threadIdx.x&31;
    size_t e=(size_t)blockIdx.x*8+warp;
    const float* h2=g_H2+e*256;
    int j=lane*4;
    float4 f=*(const float4*)(h2+j);
    float4 c=*(const float4*)(h2+128+j);
    float fr[4]={f.x,f.y,f.z,f.w}, cr[4]={c.x,c.y,c.z,c.w}, o[4];
    #pragma unroll
    for(int s=0;s<4;s++){
        int jj=j+s;
        float fv=g_affA[jj]*fr[s]+g_affC[jj];
        float cv=g_affA[128+jj]*cr[s]+g_affC[128+jj];
        float sg=1.f/(1.f+__expf(-fv));
        float sp=fmaxf(cv,0.f)+log1pf(__expf(-fabsf(cv)));
        o[s]=sg*sp;
    }
    float* dst=g_h+(size_t)nbr[e]*128+j;
    red4(dst,o[0],o[1],o[2],o[3]);
}

// ---------------- h_spec (FFMA2, V-chunk 32): per-batch Einv^T @ hb ----------------
__global__ __launch_bounds__(256) void k_spec(const float* __restrict__ eigs){
    __shared__ float As[32*128];
    __shared__ float Bs[32*128];
    int t=threadIdx.x, ty=t>>4, tx=t&15;
    int b=blockIdx.x>>2, c=blockIdx.x&3;
    int v0=c*512;
    const float* Abase=eigs+((size_t)b*4097+1+2048)*128;
    const float* Hbase=g_h+((size_t)b*2048)*128;
    int vr=t>>4, cq=(t&15)*8;
    uint64_t acc[8][4]={};
    for(int vt=0;vt<512;vt+=32){
        #pragma unroll
        for(int hq=0;hq<2;hq++){
            int vrr=vr+hq*16;
            const float* ap=Abase+(size_t)(v0+vt+vrr)*128+cq;
            *(float4*)&As[vrr*128+cq]  =*(const float4*)ap;
            *(float4*)&As[vrr*128+cq+4]=*(const float4*)(ap+4);
            const float* bp=Hbase+(size_t)(v0+vt+vrr)*128+cq;
            *(float4*)&Bs[vrr*128+cq]  =*(const float4*)bp;
            *(float4*)&Bs[vrr*128+cq+4]=*(const float4*)(bp+4);
        }
        __syncthreads();
        #pragma unroll
        for(int vv=0;vv<32;vv++){
            float4 a0=*(const float4*)&As[vv*128+ty*8];
            float4 a1=*(const float4*)&As[vv*128+ty*8+4];
            ulonglong2 q0=*(const ulonglong2*)&Bs[vv*128+tx*8];
            ulonglong2 q1=*(const ulonglong2*)&Bs[vv*128+tx*8+4];
            uint64_t bp2[4]={q0.x,q0.y,q1.x,q1.y};
            float aa[8]={a0.x,a0.y,a0.z,a0.w,a1.x,a1.y,a1.z,a1.w};
            #pragma unroll
            for(int ri=0;ri<8;ri++){
                uint64_t ad=dup2(aa[ri]);
                #pragma unroll
                for(int cp=0;cp<4;cp++) ffma2(acc[ri][cp],ad,bp2[cp]);
            }
        }
        __syncthreads();
    }
    float* dst=g_hspec+(size_t)b*16384;
    #pragma unroll
    for(int ri=0;ri<8;ri++){
        #pragma unroll
        for(int cp=0;cp<4;cp++){
            float2 p=unp2(acc[ri][cp]);
            atomicAdd(&dst[(ty*8+ri)*128+tx*8+2*cp],  p.x);
            atomicAdd(&dst[(ty*8+ri)*128+tx*8+2*cp+1],p.y);
        }
    }
}

// ---------------- h_spec *= exp(-lam*t) ----------------
__global__ void k_coeff(const float* __restrict__ eigs, const float* __restrict__ pt){
    int i=blockIdx.x*blockDim.x+threadIdx.x;
    int b=i>>14, k=(i>>7)&127, hcol=i&127;
    float lam=eigs[(size_t)b*4097*128+k];
    float tt=fmaxf(pt[hcol],1e-6f);
    g_hspec[i]*=__expf(-lam*tt);
}

// ---------------- h += affA*y2 + affC ----------------
__global__ void k_update(){
    size_t i=(size_t)blockIdx.x*blockDim.x+threadIdx.x;
    int j=(int)((i*4)&127);
    float4 y=((const float4*)g_y2)[i];
    float4 h=((float4*)g_h)[i];
    h.x+=g_affA[j+0]*y.x+g_affC[j+0];
    h.y+=g_affA[j+1]*y.y+g_affC[j+1];
    h.z+=g_affA[j+2]*y.z+g_affC[j+2];
    h.w+=g_affA[j+3]*y.w+g_affC[j+3];
    ((float4*)g_h)[i]=h;
}

// ---------------- final projection + mean over V ----------------
__global__ __launch_bounds__(256) void k_out(const float* __restrict__ wo2){
    __shared__ float part[8];
    int warp=threadIdx.x>>5, lane=threadIdx.x&31;
    size_t row=(size_t)blockIdx.x*8+warp;
    int j=lane*4;
    float4 y=*(const float4*)&g_y1[row*128+j];
    float4 w=*(const float4*)&wo2[j];
    float v=0.f;
    v+=siluf(g_affA[j+0]*y.x+g_affC[j+0])*w.x;
    v+=siluf(g_affA[j+1]*y.y+g_affC[j+1])*w.y;
    v+=siluf(g_affA[j+2]*y.z+g_affC[j+2])*w.z;
    v+=siluf(g_affA[j+3]*y.w+g_affC[j+3])*w.w;
    #pragma unroll
    for(int s=16;s>0;s>>=1) v+=__shfl_xor_sync(0xffffffffu,v,s);
    if(lane==0) part[warp]=v;
    __syncthreads();
    if(threadIdx.x==0){
        float s=0.f;
        #pragma unroll
        for(int q=0;q<8;q++) s+=part[q];
        atomicAdd(&g_outacc[blockIdx.x>>8],s);
    }
}

__global__ void k_final(float* out, const float* __restrict__ bo2){
    int b=threadIdx.x;
    if(b<BB) out[b]=g_outacc[b]*(1.f/(float)VV)+bo2[0];
}

// ---------------- launch ----------------
extern "C" void kernel_launch(void* const* d_in, const int* in_sizes, int n_in,
                              void* d_out, int out_size){
    const float* chem =(const float*)d_in[0];
    const int*   nbr  =(const int*)  d_in[1];
    const float* eigs =(const float*)d_in[2];
    const float* w1   =(const float*)d_in[3];
    const float* b1   =(const float*)d_in[4];
    const float* g1   =(const float*)d_in[5];
    const float* be1  =(const float*)d_in[6];
    const float* w2   =(const float*)d_in[7];
    const float* b2   =(const float*)d_in[8];
    const float* g2   =(const float*)d_in[9];
    const float* be2  =(const float*)d_in[10];
    const float* prop =(const float*)d_in[11];
    const float* pw1  =(const float*)d_in[12];
    const float* pb1  =(const float*)d_in[13];
    const float* pg1  =(const float*)d_in[14];
    const float* pbe1 =(const float*)d_in[15];
    const float* pw2  =(const float*)d_in[16];
    const float* pb2  =(const float*)d_in[17];
    const float* pg2  =(const float*)d_in[18];
    const float* pbe2 =(const float*)d_in[19];
    const float* wo1  =(const float*)d_in[20];
    const float* bo1  =(const float*)d_in[21];
    const float* go1  =(const float*)d_in[22];
    const float* beo1 =(const float*)d_in[23];
    const float* wo2  =(const float*)d_in[24];
    const float* bo2  =(const float*)d_in[25];
    (void)in_sizes; (void)n_in; (void)out_size;

    k_zero_h<<<4096,1024>>>();
    k_zero_st<<<1,256>>>();
    k_gemm1<<<EE/128,256>>>(chem,w1,b1);
    k_fold<<<1,256>>>(128,1.f/(float)EE,g1,be1);
    k_zero_st<<<1,256>>>();
    k_mm<<<dim3(EE/128,2),256>>>(2,0,0,nullptr,w2,256,b2,256,128,1);
    k_fold<<<1,256>>>(256,1.f/(float)EE,g2,be2);
    k_msg<<<EE/8,256>>>(nbr);

    for(int l=0;l<3;l++){
        k_zero_spec<<<256,1024>>>();
        k_spec<<<256,256>>>(eigs);
        k_coeff<<<4096,256>>>(eigs,prop+l*128);
        k_mm<<<dim3(NNODE/128,1),256>>>(3,1,1,eigs,nullptr,128,nullptr,128,128,0);
        k_zero_st<<<1,256>>>();
        k_mm<<<dim3(NNODE/128,1),256>>>(1,1,2,nullptr,pw1+(size_t)l*256*128,128,pb1+l*128,128,256,1);
        k_fold<<<1,256>>>(128,1.f/(float)NNODE,pg1+l*128,pbe1+l*128);
        k_zero_st<<<1,256>>>();
        k_mm<<<dim3(NNODE/128,1),256>>>(2,2,3,nullptr,pw2+(size_t)l*128*128,128,pb2+l*128,128,128,1);
        k_fold<<<1,256>>>(128,1.f/(float)NNODE,pg2+l*128,pbe2+l*128);
        k_update<<<16384,256>>>();
    }

    k_zero_st<<<1,256>>>();
    k_mm<<<dim3(NNODE/128,1),256>>>(0,1,2,nullptr,wo1,128,bo1,128,128,1);
    k_fold<<<1,256>>>(128,1.f/(float)NNODE,go1,beo1);
    k_out<<<NNODE/8,256>>>(wo2);
    k_final<<<1,64>>>((float*)d_out,bo2);
}